// round 11
// baseline (speedup 1.0000x reference)
#include <cuda_runtime.h>

#define BATCH 1024
#define FEAT 256
#define NUM_CLASSES 100000
#define CLAMP_MIN 1e-12f
#define CLAMP_MAX 1e12f
#define WARPS_PER_BLOCK 8
#define ROWS_PER_BLOCK WARPS_PER_BLOCK
#define NUM_BLOCKS (BATCH / ROWS_PER_BLOCK)   // 128

// Packed cross-block accumulator:
//   bits [52:64) = arrived-block count, bits [0:52) = sum in 2^-20 fixed point.
// Block partials are positive (clamped >= 1e-12) and < 2^19 * 8, so the fixed
// sum fits well under 2^52; count 128 < 2^12. One relaxed u64 RMW carries both
// the data and the "am I last?" ticket -> no fence, no second atomic, no final
// load. Quantization <= 2^-21 abs per block -> ~1e-10 relative on loss ~512.
#define COUNT_ONE (1ULL << 52)
#define SUM_MASK  (COUNT_ONE - 1ULL)
#define FIX_SCALE 1048576.0   // 2^20

__device__ unsigned long long g_pack = 0ULL;   // zero at load; reset by last block

__global__ __launch_bounds__(WARPS_PER_BLOCK * 32)
void center_loss_kernel(const float* __restrict__ x,
                        const float* __restrict__ centers,
                        const int* __restrict__ labels,   // int32, in [0, NUM_CLASSES)
                        float* __restrict__ out) {
    const int warp = threadIdx.x >> 5;
    const int lane = threadIdx.x & 31;
    const int row  = blockIdx.x * ROWS_PER_BLOCK + warp;

    // Label load heads the longest dependent chain: label -> address -> gather.
    const int lbl = __ldg(&labels[row]);

    const float4* xr = reinterpret_cast<const float4*>(x + (size_t)row * FEAT);
    const float4* cr = reinterpret_cast<const float4*>(centers + (size_t)lbl * FEAT);

    // x loads are independent of the label -> in flight during the label wait.
    float4 a0 = __ldg(&xr[lane]);
    float4 a1 = __ldg(&xr[lane + 32]);
    float sx = a0.x*a0.x + a0.y*a0.y + a0.z*a0.z + a0.w*a0.w
             + a1.x*a1.x + a1.y*a1.y + a1.z*a1.z + a1.w*a1.w;

    float4 b0 = __ldg(&cr[lane]);
    float4 b1 = __ldg(&cr[lane + 32]);
    float sc  = b0.x*b0.x + b0.y*b0.y + b0.z*b0.z + b0.w*b0.w
              + b1.x*b1.x + b1.y*b1.y + b1.z*b1.z + b1.w*b1.w;
    float sxc = a0.x*b0.x + a0.y*b0.y + a0.z*b0.z + a0.w*b0.w
              + a1.x*b1.x + a1.y*b1.y + a1.z*b1.z + a1.w*b1.w;

    float p = sx + sc - 2.0f * sxc;

    // Warp reduction.
    #pragma unroll
    for (int off = 16; off > 0; off >>= 1)
        p += __shfl_xor_sync(0xFFFFFFFFu, p, off);

    __shared__ float bs[WARPS_PER_BLOCK];
    if (lane == 0)
        bs[warp] = fminf(fmaxf(p, CLAMP_MIN), CLAMP_MAX);   // clamp per row
    __syncthreads();

    // Warp 0: parallel reduce of the 8 warp partials, then one packed RMW.
    if (warp == 0 && lane < 8) {
        float s = bs[lane];
        #pragma unroll
        for (int off = 4; off > 0; off >>= 1)
            s += __shfl_xor_sync(0x000000FFu, s, off);

        if (lane == 0) {
            const unsigned long long val =
                COUNT_ONE + (unsigned long long)__double2ll_rn((double)s * FIX_SCALE);
            const unsigned long long old = atomicAdd(&g_pack, val);

            if ((old >> 52) == NUM_BLOCKS - 1) {
                // Last block: old+val holds the complete fixed-point sum.
                const unsigned long long sum_fix = (old + val) & SUM_MASK;
                const double tot = (double)sum_fix * (1.0 / FIX_SCALE);
                *out = (float)(tot * (1.0 / BATCH)
                             + (double)(NUM_CLASSES - 1) * 1e-12);
                g_pack = 0ULL;   // re-arm for next graph replay
            }
        }
    }
}

extern "C" void kernel_launch(void* const* d_in, const int* in_sizes, int n_in,
                              void* d_out, int out_size) {
    // Resolve inputs by element count:
    //   x: 1024*256 = 262144, centers: 100000*256 = 25600000, labels: 1024
    const float* x = nullptr;
    const float* centers = nullptr;
    const int*   labels = nullptr;
    for (int i = 0; i < n_in; i++) {
        if (in_sizes[i] == BATCH * FEAT)            x       = (const float*)d_in[i];
        else if (in_sizes[i] == NUM_CLASSES * FEAT) centers = (const float*)d_in[i];
        else                                        labels  = (const int*)d_in[i];
    }
    center_loss_kernel<<<NUM_BLOCKS, WARPS_PER_BLOCK * 32>>>(
        x, centers, labels, (float*)d_out);
}

// round 12
// speedup vs baseline: 1.0644x; 1.0644x over previous
#include <cuda_runtime.h>

#define BATCH 1024
#define FEAT 256
#define NUM_CLASSES 100000
#define CLAMP_MIN 1e-12f
#define CLAMP_MAX 1e12f
#define WARPS_PER_BLOCK 8
#define ROWS_PER_BLOCK WARPS_PER_BLOCK
#define NUM_BLOCKS (BATCH / ROWS_PER_BLOCK)   // 128

// Packed cross-block accumulator:
//   bits [52:64) = arrived-block count, bits [0:52) = sum in 2^-20 fixed point.
// Block partials are positive (clamped >= 1e-12) and < 2^19 * 8, so the fixed
// sum fits well under 2^52; count 128 < 2^12. One relaxed u64 RMW carries both
// the data and the "am I last?" ticket -> no fence, no second atomic, no final
// load. Quantization <= 2^-21 abs per block -> ~1e-10 relative on loss ~512.
#define COUNT_ONE (1ULL << 52)
#define SUM_MASK  (COUNT_ONE - 1ULL)
#define FIX_SCALE 1048576.0   // 2^20

__device__ unsigned long long g_pack = 0ULL;   // zero at load; reset by last block

__global__ __launch_bounds__(WARPS_PER_BLOCK * 32)
void center_loss_kernel(const float* __restrict__ x,
                        const float* __restrict__ centers,
                        const int* __restrict__ labels,   // int32, in [0, NUM_CLASSES)
                        float* __restrict__ out) {
    const int warp = threadIdx.x >> 5;
    const int lane = threadIdx.x & 31;
    const int row  = blockIdx.x * ROWS_PER_BLOCK + warp;

    // Label load heads the longest dependent chain: label -> address -> gather.
    const int lbl = __ldg(&labels[row]);

    const float4* xr = reinterpret_cast<const float4*>(x + (size_t)row * FEAT);
    const float4* cr = reinterpret_cast<const float4*>(centers + (size_t)lbl * FEAT);

    // x loads are independent of the label -> in flight during the label wait.
    float4 a0 = __ldg(&xr[lane]);
    float4 a1 = __ldg(&xr[lane + 32]);
    float sx = a0.x*a0.x + a0.y*a0.y + a0.z*a0.z + a0.w*a0.w
             + a1.x*a1.x + a1.y*a1.y + a1.z*a1.z + a1.w*a1.w;

    float4 b0 = __ldg(&cr[lane]);
    float4 b1 = __ldg(&cr[lane + 32]);
    float sc  = b0.x*b0.x + b0.y*b0.y + b0.z*b0.z + b0.w*b0.w
              + b1.x*b1.x + b1.y*b1.y + b1.z*b1.z + b1.w*b1.w;
    float sxc = a0.x*b0.x + a0.y*b0.y + a0.z*b0.z + a0.w*b0.w
              + a1.x*b1.x + a1.y*b1.y + a1.z*b1.z + a1.w*b1.w;

    float p = sx + sc - 2.0f * sxc;

    // Warp reduction.
    #pragma unroll
    for (int off = 16; off > 0; off >>= 1)
        p += __shfl_xor_sync(0xFFFFFFFFu, p, off);

    __shared__ float bs[WARPS_PER_BLOCK];
    if (lane == 0)
        bs[warp] = fminf(fmaxf(p, CLAMP_MIN), CLAMP_MAX);   // clamp per row
    __syncthreads();

    // Warp 0: parallel reduce of the 8 warp partials, then one packed RMW.
    if (warp == 0 && lane < 8) {
        float s = bs[lane];
        #pragma unroll
        for (int off = 4; off > 0; off >>= 1)
            s += __shfl_xor_sync(0x000000FFu, s, off);

        if (lane == 0) {
            const unsigned long long val =
                COUNT_ONE + (unsigned long long)__double2ll_rn((double)s * FIX_SCALE);
            const unsigned long long old = atomicAdd(&g_pack, val);

            if ((old >> 52) == NUM_BLOCKS - 1) {
                // Last block: old+val holds the complete fixed-point sum.
                const unsigned long long sum_fix = (old + val) & SUM_MASK;
                const double tot = (double)sum_fix * (1.0 / FIX_SCALE);
                *out = (float)(tot * (1.0 / BATCH)
                             + (double)(NUM_CLASSES - 1) * 1e-12);
                g_pack = 0ULL;   // re-arm for next graph replay
            }
        }
    }
}

extern "C" void kernel_launch(void* const* d_in, const int* in_sizes, int n_in,
                              void* d_out, int out_size) {
    // Resolve inputs by element count:
    //   x: 1024*256 = 262144, centers: 100000*256 = 25600000, labels: 1024
    const float* x = nullptr;
    const float* centers = nullptr;
    const int*   labels = nullptr;
    for (int i = 0; i < n_in; i++) {
        if (in_sizes[i] == BATCH * FEAT)            x       = (const float*)d_in[i];
        else if (in_sizes[i] == NUM_CLASSES * FEAT) centers = (const float*)d_in[i];
        else                                        labels  = (const int*)d_in[i];
    }
    center_loss_kernel<<<NUM_BLOCKS, WARPS_PER_BLOCK * 32>>>(
        x, centers, labels, (float*)d_out);
}